// round 11
// baseline (speedup 1.0000x reference)
#include <cuda_runtime.h>
#include <math.h>

#define NB 4
#define NC 31
#define NK 16                 // Hermitian half of C-spectrum
#define SLICE 16384           // 128*128
#define VOL   (NB*NC*SLICE)   // 2031616

// ---------------- static scratch --------------------------------------------
__device__ float  g_Z[VOL];
__device__ float  g_M[VOL];       // M = mu1*X + G1
__device__ float  g_G1[VOL];
__device__ float  g_Ph[2][VOL];
__device__ float  g_Pv[2][VOL];
__device__ float  g_Ps[VOL];
__device__ float2 g_S[NB*NK*SLICE];   // spectral working buffer

// ---------------- helpers ---------------------------------------------------
__device__ __forceinline__ float shrinkf(float x, float t) {
    return copysignf(fmaxf(fabsf(x) - t, 0.0f), x);
}
__device__ __forceinline__ float2 cadd(float2 a, float2 b){ return make_float2(a.x+b.x, a.y+b.y); }
__device__ __forceinline__ float2 csub(float2 a, float2 b){ return make_float2(a.x-b.x, a.y-b.y); }
__device__ __forceinline__ float2 cmuln(float2 d, float2 w){   // d * (wx - i*wy)
    return make_float2(d.x*w.x + d.y*w.y, d.y*w.x - d.x*w.y);
}
__device__ __forceinline__ float2 cmulp(float2 d, float2 w){   // d * (wx + i*wy)
    return make_float2(d.x*w.x - d.y*w.y, d.x*w.y + d.y*w.x);
}
__device__ __forceinline__ float2 shfl2(float2 v, int m){
    float2 r;
    r.x = __shfl_xor_sync(0xffffffffu, v.x, m);
    r.y = __shfl_xor_sync(0xffffffffu, v.y, m);
    return r;
}
// flat [c][k] table: twck[c*NK+k] = (cos, -sin)(2*pi*k*c/31)
__device__ __forceinline__ void build_twck(float2* twck, int tid, int nthr){
    for (int e = tid; e < NC*NK; e += nthr){
        int c = e >> 4, k = e & 15;
        int m = (k * c) % NC;
        float s, co; sincospif((float)m * (2.f/31.f), &s, &co);
        twck[e] = make_float2(co, -s);
    }
}

// ---------------- warp-level 128-pt FFT (4 complex per lane) -----------------
__device__ __forceinline__ void wfft_fwd(float2 v[4], const float2* __restrict__ twd, int t){
    {   // hs=6
        float2 w0 = twd[t], w1 = twd[32 + t];
        float2 a = v[0], b = v[2]; v[0] = cadd(a,b); v[2] = cmuln(csub(a,b), w0);
        a = v[1]; b = v[3]; v[1] = cadd(a,b); v[3] = cmuln(csub(a,b), w1);
    }
    {   // hs=5
        float2 w = twd[2*t];
        float2 a = v[0], b = v[1]; v[0] = cadd(a,b); v[1] = cmuln(csub(a,b), w);
        a = v[2]; b = v[3]; v[2] = cadd(a,b); v[3] = cmuln(csub(a,b), w);
    }
    #pragma unroll
    for (int hs = 4; hs >= 0; hs--){
        int half = 1 << hs;
        float2 w = twd[(t & (half-1)) << (6 - hs)];
        bool up = (t & half) != 0;
        #pragma unroll
        for (int j = 0; j < 4; j++){
            float2 pv = shfl2(v[j], half);
            v[j] = up ? cmuln(csub(pv, v[j]), w) : cadd(v[j], pv);
        }
    }
}

__device__ __forceinline__ void wfft_inv(float2 v[4], const float2* __restrict__ twd, int t){
    #pragma unroll
    for (int hs = 0; hs <= 4; hs++){
        int half = 1 << hs;
        float2 w = twd[(t & (half-1)) << (6 - hs)];
        bool up = (t & half) != 0;
        #pragma unroll
        for (int j = 0; j < 4; j++){
            float2 u = up ? cmulp(v[j], w) : v[j];
            float2 pu = shfl2(u, half);
            v[j] = up ? csub(pu, u) : cadd(u, pu);
        }
    }
    {   // hs=5
        float2 w = twd[2*t];
        float2 tm = cmulp(v[1], w); float2 x0 = v[0]; v[0] = cadd(x0,tm); v[1] = csub(x0,tm);
        tm = cmulp(v[3], w); x0 = v[2]; v[2] = cadd(x0,tm); v[3] = csub(x0,tm);
    }
    {   // hs=6
        float2 w0 = twd[t], w1 = twd[32 + t];
        float2 tm = cmulp(v[2], w0); float2 x0 = v[0]; v[0] = cadd(x0,tm); v[2] = csub(x0,tm);
        tm = cmulp(v[3], w1); x0 = v[1]; v[1] = cadd(x0,tm); v[3] = csub(x0,tm);
    }
}

// ---------------- init ------------------------------------------------------
__global__ void k_init(const float* __restrict__ Y, float mu1_0) {
    int i = blockIdx.x * blockDim.x + threadIdx.x;
    if (i >= VOL) return;
    float y = Y[i];
    g_Z[i] = y;
    g_M[i] = mu1_0 * y;
    g_G1[i] = 0.f;
    g_Ph[0][i] = 0.f; g_Pv[0][i] = 0.f; g_Ps[i] = 0.f;
}

// ---------------- fused: pencil phase + real C-DFT + forward row FFT --------
// 512 threads: 128 pencils x 4 c-range quarters. grid = 512 blocks.
__global__ __launch_bounds__(512, 3) void k_cfwd_rows(int pp, float mu2,
                                                      float mu2p, float inv_mu2, float thr)
{
    __shared__ float2 twck[NC*NK];
    __shared__ float2 twd[64];
    __shared__ float  numer[NC*128];   // 15.5KB
    __shared__ float2 sF[NK*128];      // 16KB

    int tid = threadIdx.x;
    build_twck(twck, tid, 512);
    if (tid < 64){ float s, c; sincospif((float)tid*(1.f/64.f), &s, &c); twd[tid] = make_float2(c, s); }

    int pl = tid & 127;        // pencil within block (== w)
    int q  = tid >> 7;         // c-quarter 0..3
    int n  = blockIdx.x >> 7;
    int h  = blockIdx.x & 127;
    int w  = pl;

    int ow1 = ((w + 1)   & 127) - w;
    int owm = ((w + 127) & 127) - w;
    int oh1 = ((((h + 1)   & 127) - h) << 7);
    int ohm = ((((h + 127) & 127) - h) << 7);
    int base = n * (NC * SLICE) + (h << 7) + w;

    const float* __restrict__ Ph_in  = g_Ph[pp];
    float*       __restrict__ Ph_out = g_Ph[pp ^ 1];
    const float* __restrict__ Pv_in  = g_Pv[pp];
    float*       __restrict__ Pv_out = g_Pv[pp ^ 1];

    int c_lo  = q << 3;
    int c_hi  = (q == 3) ? 31 : c_lo + 8;
    int cprev = (c_lo == 0) ? 30 : c_lo - 1;

    // boundary pre-reads (must precede ANY g_Ps write in this block)
    float z_lo = g_Z[base + c_lo * SLICE];
    float zp   = g_Z[base + cprev * SLICE];
    float Psp  = g_Ps[base + cprev * SLICE];
    __syncthreads();   // tables ready AND boundary reads ordered before loop writes

    float As_prev;
    {
        float d  = zp - z_lo;
        float g2 = Psp - mu2p * d;
        float qq = g2 * inv_mu2;
        As_prev  = shrinkf(d - qq, thr) + qq;
    }

    // ---- phase 1: pencil math for this thread's c-quarter ----
    float zc = z_lo;
    for (int c = c_lo; c < c_hi; c++) {
        int i = base + c * SLICE;
        int cn = (c == 30) ? 0 : c + 1;
        float znext = g_Z[base + cn * SLICE];
        float zw1 = g_Z[i + ow1], zwm = g_Z[i + owm];
        float zh1 = g_Z[i + oh1], zhm = g_Z[i + ohm];

        float dh  = zc - zw1;
        float g2h = Ph_in[i] - mu2p * dh;
        float qh  = g2h * inv_mu2;
        float Ah  = shrinkf(dh - qh, thr) + qh;
        Ph_out[i] = mu2 * Ah;
        float dhm  = zwm - zc;
        float g2hm = Ph_in[i + owm] - mu2p * dhm;
        float qhm  = g2hm * inv_mu2;
        float Ahm  = shrinkf(dhm - qhm, thr) + qhm;

        float dv  = zc - zh1;
        float g2v = Pv_in[i] - mu2p * dv;
        float qv  = g2v * inv_mu2;
        float Av  = shrinkf(dv - qv, thr) + qv;
        Pv_out[i] = mu2 * Av;
        float dvm  = zhm - zc;
        float g2vm = Pv_in[i + ohm] - mu2p * dvm;
        float qvm  = g2vm * inv_mu2;
        float Avm  = shrinkf(dvm - qvm, thr) + qvm;

        float ds  = zc - znext;
        float g2s = g_Ps[i] - mu2p * ds;
        float qs  = g2s * inv_mu2;
        float As  = shrinkf(ds - qs, thr) + qs;
        g_Ps[i]   = mu2 * As;

        numer[c * 128 + pl] = g_M[i]
                    + mu2 * ((Ah - Ahm) + (Av - Avm) + (As - As_prev));
        As_prev = As;
        zc = znext;
    }
    __syncthreads();

    // ---- phase 2: real 31-pt DFT; thread q computes k in [4q, 4q+4) ----
    float2 F[4];
    #pragma unroll
    for (int kk = 0; kk < 4; kk++) F[kk] = make_float2(0.f, 0.f);
    int k0 = q << 2;
    for (int c = 0; c < NC; c++) {
        float nu = numer[c * 128 + pl];
        const float2* tc = twck + (c << 4) + k0;
        #pragma unroll
        for (int kk = 0; kk < 4; kk++) {
            float2 t = tc[kk];
            F[kk].x = fmaf(nu, t.x, F[kk].x);
            F[kk].y = fmaf(nu, t.y, F[kk].y);
        }
    }
    #pragma unroll
    for (int kk = 0; kk < 4; kk++) sF[(k0 + kk)*128 + pl] = F[kk];
    __syncthreads();

    // ---- phase 3: forward row FFT: 16 warps <-> 16 k ----
    int wid = tid >> 5, t = tid & 31;
    float2 v[4];
    #pragma unroll
    for (int j = 0; j < 4; j++) v[j] = sF[wid*128 + t + 32*j];
    wfft_fwd(v, twd, t);
    float2* dst = g_S + (size_t)(n*NK + wid)*SLICE + (h << 7);
    #pragma unroll
    for (int j = 0; j < 4; j++) dst[t + 32*j] = v[j];
}

// ---------------- fused: col fwd FFT + spectral divide + col inv FFT --------
__global__ __launch_bounds__(256) void k_ccols(float mu1, float mu2){
    __shared__ float2 twd[64];
    __shared__ float  d128s[128];   // 2-2cos(2*pi*brev(pos)/128), by POSITION
    __shared__ float2 sT[16*129];
    int tid = threadIdx.x;
    if (tid < 64){ float s, c; sincospif((float)tid*(1.f/64.f), &s, &c); twd[tid] = make_float2(c, s); }
    if (tid < 128){
        int f = __brev((unsigned)tid) >> 25;
        d128s[tid] = 2.f - 2.f * cospif((float)f * (1.f/64.f));
    }

    int s  = blockIdx.x >> 3;
    int w0 = (blockIdx.x & 7) << 4;
    int kc = s & (NK - 1);
    float dck = 2.f - 2.f * cospif((float)kc * (2.f/31.f));

    const float2* src = g_S + (size_t)s * SLICE + w0;
    for (int idx = tid; idx < 2048; idx += 256){
        int h = idx >> 4, wl = idx & 15;
        sT[wl*129 + h] = src[h*128 + wl];
    }
    __syncthreads();

    int wid = tid >> 5, t = tid & 31;
    #pragma unroll
    for (int ci = 0; ci < 2; ci++){
        int wl = wid*2 + ci;
        float2 v[4];
        #pragma unroll
        for (int j = 0; j < 4; j++) v[j] = sT[wl*129 + t + 32*j];
        wfft_fwd(v, twd, t);
        float dw = d128s[w0 + wl];
        #pragma unroll
        for (int j = 0; j < 4; j++){
            float sc = __fdividef(6.103515625e-05f,      // 1/16384
                                  mu1 + mu2 * (dck + d128s[t + 32*j] + dw));
            v[j].x *= sc; v[j].y *= sc;
        }
        wfft_inv(v, twd, t);
        #pragma unroll
        for (int j = 0; j < 4; j++) sT[wl*129 + t + 32*j] = v[j];
    }
    __syncthreads();

    float2* dst = g_S + (size_t)s * SLICE + w0;
    for (int idx = tid; idx < 2048; idx += 256){
        int h = idx >> 4, wl = idx & 15;
        dst[h*128 + wl] = sT[wl*129 + h];
    }
}

// ---------------- Hermitian C-synthesis chunk loop (templated, no macro) -----
// Lane layout: q = tid&3 (k-quarter), w = tid>>2 (pencil). Each thread holds
// partial H sums for 4 k's; a 2-stage shfl_xor butterfly assembles full sums
// so lane q ends up owning c = cb+q of every 4-c chunk.
template<bool FINAL>
__device__ __forceinline__ void csynth_loop(
    const float2* __restrict__ twck, const float* Hx, const float* Hy,
    int k0, int q, int base,
    float mu1, float mu1n,
    const float* __restrict__ Y, const float* __restrict__ inW,
    float* __restrict__ out)
{
    int b0 = q & 1, b1 = q >> 1;
    for (int cb = 0; cb < 32; cb += 4) {
        float V[4];
        #pragma unroll
        for (int j = 0; j < 4; j++) {
            int cc = cb + j; cc = (cc > 30) ? 30 : cc;
            const float2* tc = twck + (cc << 4) + k0;
            float a = 0.f;
            #pragma unroll
            for (int kk = 0; kk < 4; kk++) {
                float2 tt = tc[kk];
                a = fmaf(Hx[kk], tt.x, a);
                a = fmaf(Hy[kk], tt.y, a);
            }
            V[j] = a;
        }
        float e0 = __shfl_xor_sync(0xffffffffu, V[0], 1);
        float e1 = __shfl_xor_sync(0xffffffffu, V[1], 1);
        float e2 = __shfl_xor_sync(0xffffffffu, V[2], 1);
        float e3 = __shfl_xor_sync(0xffffffffu, V[3], 1);
        float s0 = b0 ? (V[1] + e1) : (V[0] + e0);
        float s1 = b0 ? (V[3] + e3) : (V[2] + e2);
        float t0 = __shfl_xor_sync(0xffffffffu, s0, 2);
        float t1 = __shfl_xor_sync(0xffffffffu, s1, 2);
        float acc = b1 ? (s1 + t1) : (s0 + t0);
        int c = cb + q;
        if (c < 31) {
            int i = base + c * SLICE;
            if (FINAL) {
                out[i] = acc;
            } else {
                g_Z[i] = acc;
                float xw = inW[i], y = Y[i], g1 = g_G1[i];
                float x = __fdividef(fmaf(xw, y, fmaf(mu1, acc, -g1)), xw + mu1);
                float g1n = fmaf(mu1, x - acc, g1);
                g_G1[i] = g1n;
                g_M[i]  = fmaf(mu1n, x, g1n);
            }
        }
    }
}

// ---------------- fused: inverse row FFT + Hermitian C-synthesis + update ---
__global__ __launch_bounds__(512, 4) void k_irows_cinv(const float* __restrict__ Y,
                                                       const float* __restrict__ inW,
                                                       float mu1, float mu1n,
                                                       float* __restrict__ out)
{
    __shared__ float2 twd[64];
    __shared__ float2 twck[NC*NK];
    __shared__ float2 sH[NK*129];    // stride 129: conflict-free k-split reads
    int tid = threadIdx.x;
    if (tid < 64){ float s, c; sincospif((float)tid*(1.f/64.f), &s, &c); twd[tid] = make_float2(c, s); }
    build_twck(twck, tid, 512);
    __syncthreads();

    int n = blockIdx.x >> 7, h = blockIdx.x & 127;
    int wid = tid >> 5, t = tid & 31;
    {
        const float2* src = g_S + (size_t)(n*NK + wid)*SLICE + h*128;
        float2 v[4];
        #pragma unroll
        for (int j = 0; j < 4; j++) v[j] = src[t + 32*j];
        wfft_inv(v, twd, t);
        #pragma unroll
        for (int j = 0; j < 4; j++) sH[wid*129 + t + 32*j] = v[j];
    }
    __syncthreads();

    int q = tid & 3;           // k-quarter
    int w = tid >> 2;          // pencil 0..127
    int k0 = q << 2;
    float Hx[4], Hy[4];
    const float i31 = 1.f/31.f, i31x2 = 2.f/31.f;
    #pragma unroll
    for (int j = 0; j < 4; j++){
        float2 v = sH[(k0 + j)*129 + w];
        Hx[j] = v.x * i31x2;
        Hy[j] = v.y * i31x2;
    }
    if (q == 0) { Hx[0] = sH[w].x * i31; Hy[0] = 0.f; }

    int base = n * (NC * SLICE) + (h << 7) + w;
    if (out != nullptr)
        csynth_loop<true >(twck, Hx, Hy, k0, q, base, mu1, mu1n, Y, inW, out);
    else
        csynth_loop<false>(twck, Hx, Hy, k0, q, base, mu1, mu1n, Y, inW, out);
}

// ---------------- launch ----------------------------------------------------
extern "C" void kernel_launch(void* const* d_in, const int* in_sizes, int n_in,
                              void* d_out, int out_size) {
    const float* Y   = (const float*)d_in[0];
    const float* inW = (const float*)d_in[1];
    float* out = (float*)d_out;

    k_init<<<(VOL + 255) / 256, 256>>>(Y, 0.1f);

    double mu1d = 0.1, mu2d = 0.1, mu2pd = 0.0;
    const double lam = 0.1;

    for (int it = 0; it < 20; it++) {
        float mu1 = (float)mu1d, mu2 = (float)mu2d, mu2p = (float)mu2pd;
        float mu1n = (float)(mu1d * 1.05);
        float inv_mu2 = (float)(1.0 / mu2d);
        float thr = (float)(lam / mu2d);
        int pp = it & 1;

        k_cfwd_rows<<<NB*128, 512>>>(pp, mu2, mu2p, inv_mu2, thr);
        k_ccols<<<NB*NK*8, 256>>>(mu1, mu2);
        k_irows_cinv<<<NB*128, 512>>>(Y, inW, mu1, mu1n, (it == 19) ? out : nullptr);

        mu2pd = mu2d;
        mu1d *= 1.05;
        mu2d *= 1.05;
    }
}

// round 12
// speedup vs baseline: 1.1549x; 1.1549x over previous
#include <cuda_runtime.h>
#include <math.h>

#define NB 4
#define NC 31
#define NK 16                 // Hermitian half of C-spectrum
#define SLICE 16384           // 128*128
#define VOL   (NB*NC*SLICE)   // 2031616

// ---------------- static scratch --------------------------------------------
__device__ float  g_Z[VOL];
__device__ float  g_M[VOL];       // M = mu1*X + G1
__device__ float  g_G1[VOL];
__device__ float  g_Ph[2][VOL];
__device__ float  g_Pv[2][VOL];
__device__ float  g_Ps[VOL];
__device__ float2 g_S[NB*NK*SLICE];   // spectral working buffer

// ---------------- helpers ---------------------------------------------------
__device__ __forceinline__ float shrinkf(float x, float t) {
    return copysignf(fmaxf(fabsf(x) - t, 0.0f), x);
}
__device__ __forceinline__ float2 cadd(float2 a, float2 b){ return make_float2(a.x+b.x, a.y+b.y); }
__device__ __forceinline__ float2 csub(float2 a, float2 b){ return make_float2(a.x-b.x, a.y-b.y); }
__device__ __forceinline__ float2 cmuln(float2 d, float2 w){   // d * (wx - i*wy)
    return make_float2(d.x*w.x + d.y*w.y, d.y*w.x - d.x*w.y);
}
__device__ __forceinline__ float2 cmulp(float2 d, float2 w){   // d * (wx + i*wy)
    return make_float2(d.x*w.x - d.y*w.y, d.x*w.y + d.y*w.x);
}
__device__ __forceinline__ float2 shfl2(float2 v, int m){
    float2 r;
    r.x = __shfl_xor_sync(0xffffffffu, v.x, m);
    r.y = __shfl_xor_sync(0xffffffffu, v.y, m);
    return r;
}
// flat [c][k] table: twck[c*NK+k] = (cos, -sin)(2*pi*k*c/31)
__device__ __forceinline__ void build_twck(float2* twck, int tid, int nthr){
    for (int e = tid; e < NC*NK; e += nthr){
        int c = e >> 4, k = e & 15;
        int m = (k * c) % NC;
        float s, co; sincospif((float)m * (2.f/31.f), &s, &co);
        twck[e] = make_float2(co, -s);
    }
}

// ---------------- warp-level 128-pt FFT (4 complex per lane) -----------------
__device__ __forceinline__ void wfft_fwd(float2 v[4], const float2* __restrict__ twd, int t){
    {   // hs=6
        float2 w0 = twd[t], w1 = twd[32 + t];
        float2 a = v[0], b = v[2]; v[0] = cadd(a,b); v[2] = cmuln(csub(a,b), w0);
        a = v[1]; b = v[3]; v[1] = cadd(a,b); v[3] = cmuln(csub(a,b), w1);
    }
    {   // hs=5
        float2 w = twd[2*t];
        float2 a = v[0], b = v[1]; v[0] = cadd(a,b); v[1] = cmuln(csub(a,b), w);
        a = v[2]; b = v[3]; v[2] = cadd(a,b); v[3] = cmuln(csub(a,b), w);
    }
    #pragma unroll
    for (int hs = 4; hs >= 0; hs--){
        int half = 1 << hs;
        float2 w = twd[(t & (half-1)) << (6 - hs)];
        bool up = (t & half) != 0;
        #pragma unroll
        for (int j = 0; j < 4; j++){
            float2 pv = shfl2(v[j], half);
            v[j] = up ? cmuln(csub(pv, v[j]), w) : cadd(v[j], pv);
        }
    }
}

__device__ __forceinline__ void wfft_inv(float2 v[4], const float2* __restrict__ twd, int t){
    #pragma unroll
    for (int hs = 0; hs <= 4; hs++){
        int half = 1 << hs;
        float2 w = twd[(t & (half-1)) << (6 - hs)];
        bool up = (t & half) != 0;
        #pragma unroll
        for (int j = 0; j < 4; j++){
            float2 u = up ? cmulp(v[j], w) : v[j];
            float2 pu = shfl2(u, half);
            v[j] = up ? csub(pu, u) : cadd(u, pu);
        }
    }
    {   // hs=5
        float2 w = twd[2*t];
        float2 tm = cmulp(v[1], w); float2 x0 = v[0]; v[0] = cadd(x0,tm); v[1] = csub(x0,tm);
        tm = cmulp(v[3], w); x0 = v[2]; v[2] = cadd(x0,tm); v[3] = csub(x0,tm);
    }
    {   // hs=6
        float2 w0 = twd[t], w1 = twd[32 + t];
        float2 tm = cmulp(v[2], w0); float2 x0 = v[0]; v[0] = cadd(x0,tm); v[2] = csub(x0,tm);
        tm = cmulp(v[3], w1); x0 = v[1]; v[1] = cadd(x0,tm); v[3] = csub(x0,tm);
    }
}

// ---------------- init ------------------------------------------------------
__global__ void k_init(const float* __restrict__ Y, float mu1_0) {
    int i = blockIdx.x * blockDim.x + threadIdx.x;
    if (i >= VOL) return;
    float y = Y[i];
    g_Z[i] = y;
    g_M[i] = mu1_0 * y;
    g_G1[i] = 0.f;
    g_Ph[0][i] = 0.f; g_Pv[0][i] = 0.f; g_Ps[i] = 0.f;
}

// ---------------- fused: pencil phase + real C-DFT + forward row FFT --------
// R8 shape: 2 threads per pencil (c-range split), 128 pencils per block,
// grid = 512 blocks x 256 threads. Boundary pre-reads hoisted (race fix).
__global__ __launch_bounds__(256, 4) void k_cfwd_rows(int pp, float mu2,
                                                      float mu2p, float inv_mu2, float thr)
{
    __shared__ float2 twck[NC*NK];
    __shared__ float2 twd[64];
    __shared__ float  buf[NK*128*2];    // 16KB union: numer[31*128] | sF[16*128] float2
    float*  numer = buf;
    float2* sF    = (float2*)buf;

    int tid = threadIdx.x;
    build_twck(twck, tid, 256);
    if (tid < 64){ float s, c; sincospif((float)tid*(1.f/64.f), &s, &c); twd[tid] = make_float2(c, s); }

    int pl = tid & 127;        // pencil within block (== w)
    int q  = tid >> 7;         // c-range half: 0 -> [0,16), 1 -> [16,31)
    int n  = blockIdx.x >> 7;
    int h  = blockIdx.x & 127;
    int w  = pl;

    int ow1 = ((w + 1)   & 127) - w;
    int owm = ((w + 127) & 127) - w;
    int oh1 = ((((h + 1)   & 127) - h) << 7);
    int ohm = ((((h + 127) & 127) - h) << 7);
    int base = n * (NC * SLICE) + (h << 7) + w;

    const float* __restrict__ Ph_in  = g_Ph[pp];
    float*       __restrict__ Ph_out = g_Ph[pp ^ 1];
    const float* __restrict__ Pv_in  = g_Pv[pp];
    float*       __restrict__ Pv_out = g_Pv[pp ^ 1];

    int c_lo  = q ? 16 : 0;
    int c_hi  = q ? 31 : 16;
    int cprev = q ? 15 : 30;

    // boundary pre-reads: must complete before the other half writes g_Ps
    float z_lo = g_Z[base + c_lo * SLICE];
    float zp   = g_Z[base + cprev * SLICE];
    float Psp  = g_Ps[base + cprev * SLICE];
    __syncthreads();   // tables ready AND boundary reads ordered before loop writes

    float As_prev;
    {
        float d  = zp - z_lo;
        float g2 = Psp - mu2p * d;
        float qq = g2 * inv_mu2;
        As_prev  = shrinkf(d - qq, thr) + qq;
    }

    // ---- phase 1: pencil math for this thread's c-range ----
    float zc = z_lo;
    for (int c = c_lo; c < c_hi; c++) {
        int i = base + c * SLICE;
        int cn = (c == 30) ? 0 : c + 1;
        float znext = g_Z[base + cn * SLICE];
        float zw1 = g_Z[i + ow1], zwm = g_Z[i + owm];
        float zh1 = g_Z[i + oh1], zhm = g_Z[i + ohm];

        float dh  = zc - zw1;
        float g2h = Ph_in[i] - mu2p * dh;
        float qh  = g2h * inv_mu2;
        float Ah  = shrinkf(dh - qh, thr) + qh;
        Ph_out[i] = mu2 * Ah;
        float dhm  = zwm - zc;
        float g2hm = Ph_in[i + owm] - mu2p * dhm;
        float qhm  = g2hm * inv_mu2;
        float Ahm  = shrinkf(dhm - qhm, thr) + qhm;

        float dv  = zc - zh1;
        float g2v = Pv_in[i] - mu2p * dv;
        float qv  = g2v * inv_mu2;
        float Av  = shrinkf(dv - qv, thr) + qv;
        Pv_out[i] = mu2 * Av;
        float dvm  = zhm - zc;
        float g2vm = Pv_in[i + ohm] - mu2p * dvm;
        float qvm  = g2vm * inv_mu2;
        float Avm  = shrinkf(dvm - qvm, thr) + qvm;

        float ds  = zc - znext;
        float g2s = g_Ps[i] - mu2p * ds;
        float qs  = g2s * inv_mu2;
        float As  = shrinkf(ds - qs, thr) + qs;
        g_Ps[i]   = mu2 * As;

        numer[c * 128 + pl] = g_M[i]
                    + mu2 * ((Ah - Ahm) + (Av - Avm) + (As - As_prev));
        As_prev = As;
        zc = znext;
    }
    __syncthreads();

    // ---- phase 2: real 31-pt DFT; thread q computes k in [8q, 8q+8) ----
    float2 F[8];
    #pragma unroll
    for (int kk = 0; kk < 8; kk++) F[kk] = make_float2(0.f, 0.f);
    int k0 = q << 3;
    for (int c = 0; c < NC; c++) {
        float nu = numer[c * 128 + pl];
        const float2* tc = twck + (c << 4) + k0;
        #pragma unroll
        for (int kk = 0; kk < 8; kk++) {
            float2 t = tc[kk];
            F[kk].x = fmaf(nu, t.x, F[kk].x);
            F[kk].y = fmaf(nu, t.y, F[kk].y);
        }
    }
    __syncthreads();   // all numer reads done before sF overwrites the buffer

    #pragma unroll
    for (int kk = 0; kk < 8; kk++) sF[(k0 + kk)*128 + pl] = F[kk];
    __syncthreads();

    // ---- phase 3: forward row FFT: 16 k-tasks, 8 warps (2 each) ----
    int wid = tid >> 5, t = tid & 31;
    #pragma unroll
    for (int ki = 0; ki < 2; ki++){
        int k = wid + ki * 8;
        float2 v[4];
        #pragma unroll
        for (int j = 0; j < 4; j++) v[j] = sF[k*128 + t + 32*j];
        wfft_fwd(v, twd, t);
        float2* dst = g_S + (size_t)(n*NK + k)*SLICE + (h << 7);
        #pragma unroll
        for (int j = 0; j < 4; j++) dst[t + 32*j] = v[j];
    }
}

// ---------------- fused: col fwd FFT + spectral divide + col inv FFT --------
// 512 threads: 16 warps <-> 16 columns (1 column per warp, was 2 serially).
__global__ __launch_bounds__(512) void k_ccols(float mu1, float mu2){
    __shared__ float2 twd[64];
    __shared__ float  d128s[128];   // 2-2cos(2*pi*brev(pos)/128), by POSITION
    __shared__ float2 sT[16*129];
    int tid = threadIdx.x;
    if (tid < 64){ float s, c; sincospif((float)tid*(1.f/64.f), &s, &c); twd[tid] = make_float2(c, s); }
    if (tid >= 64 && tid < 192){
        int e = tid - 64;
        int f = __brev((unsigned)e) >> 25;
        d128s[e] = 2.f - 2.f * cospif((float)f * (1.f/64.f));
    }

    int s  = blockIdx.x >> 3;
    int w0 = (blockIdx.x & 7) << 4;
    int kc = s & (NK - 1);
    float dck = 2.f - 2.f * cospif((float)kc * (2.f/31.f));

    const float2* src = g_S + (size_t)s * SLICE + w0;
    #pragma unroll
    for (int st = 0; st < 4; st++){
        int idx = tid + st * 512;
        int h = idx >> 4, wl = idx & 15;
        sT[wl*129 + h] = src[h*128 + wl];
    }
    __syncthreads();

    int wid = tid >> 5, t = tid & 31;
    {
        int wl = wid;
        float2 v[4];
        #pragma unroll
        for (int j = 0; j < 4; j++) v[j] = sT[wl*129 + t + 32*j];
        wfft_fwd(v, twd, t);
        float dw = d128s[w0 + wl];
        #pragma unroll
        for (int j = 0; j < 4; j++){
            float sc = __fdividef(6.103515625e-05f,      // 1/16384
                                  mu1 + mu2 * (dck + d128s[t + 32*j] + dw));
            v[j].x *= sc; v[j].y *= sc;
        }
        wfft_inv(v, twd, t);
        #pragma unroll
        for (int j = 0; j < 4; j++) sT[wl*129 + t + 32*j] = v[j];
    }
    __syncthreads();

    float2* dst = g_S + (size_t)s * SLICE + w0;
    #pragma unroll
    for (int st = 0; st < 4; st++){
        int idx = tid + st * 512;
        int h = idx >> 4, wl = idx & 15;
        dst[h*128 + wl] = sT[wl*129 + h];
    }
}

// ---------------- fused: inverse row FFT + Hermitian C-synthesis + update ---
// R8 shape: 512 threads, 31 H regs per thread, 4 c-groups of ~8 c each.
__global__ __launch_bounds__(512, 2) void k_irows_cinv(const float* __restrict__ Y,
                                                       const float* __restrict__ inW,
                                                       float mu1, float mu1n,
                                                       float* __restrict__ out)
{
    __shared__ float2 twd[64];
    __shared__ float2 twck[NC*NK];
    __shared__ float2 sH[NK*128];
    int tid = threadIdx.x;
    if (tid < 64){ float s, c; sincospif((float)tid*(1.f/64.f), &s, &c); twd[tid] = make_float2(c, s); }
    build_twck(twck, tid, 512);
    __syncthreads();

    int n = blockIdx.x >> 7, h = blockIdx.x & 127;
    int wid = tid >> 5, t = tid & 31;
    {
        const float2* src = g_S + (size_t)(n*NK + wid)*SLICE + h*128;
        float2 v[4];
        #pragma unroll
        for (int j = 0; j < 4; j++) v[j] = src[t + 32*j];
        wfft_inv(v, twd, t);
        #pragma unroll
        for (int j = 0; j < 4; j++) sH[wid*128 + t + 32*j] = v[j];
    }
    __syncthreads();

    int w = tid & 127, cg = tid >> 7;   // 4 c-groups per pencil
    float H0;
    float Hx[NK-1], Hy[NK-1];
    const float i31 = 1.f/31.f, i31x2 = 2.f/31.f;
    H0 = sH[w].x * i31;
    #pragma unroll
    for (int k = 1; k < NK; k++){
        float2 v = sH[k*128 + w];
        Hx[k-1] = v.x * i31x2; Hy[k-1] = v.y * i31x2;
    }

    int c0 = cg * 8, c1 = (cg == 3) ? 31 : c0 + 8;
    int base = n * (NC * SLICE) + h*128 + w;
    if (out != nullptr) {
        for (int c = c0; c < c1; c++){
            float acc = H0;
            const float2* tc = twck + (c << 4);
            #pragma unroll
            for (int k = 1; k < NK; k++){
                float2 tt = tc[k];
                acc = fmaf(Hx[k-1], tt.x, acc);
                acc = fmaf(Hy[k-1], tt.y, acc);
            }
            out[base + c * SLICE] = acc;
        }
    } else {
        for (int c = c0; c < c1; c++){
            float acc = H0;
            const float2* tc = twck + (c << 4);
            #pragma unroll
            for (int k = 1; k < NK; k++){
                float2 tt = tc[k];
                acc = fmaf(Hx[k-1], tt.x, acc);
                acc = fmaf(Hy[k-1], tt.y, acc);
            }
            int i = base + c * SLICE;
            g_Z[i] = acc;
            float xw = inW[i], y = Y[i], g1 = g_G1[i];
            float x = __fdividef(fmaf(xw, y, fmaf(mu1, acc, -g1)), xw + mu1);
            float g1n = fmaf(mu1, x - acc, g1);
            g_G1[i] = g1n;
            g_M[i]  = fmaf(mu1n, x, g1n);
        }
    }
}

// ---------------- launch ----------------------------------------------------
extern "C" void kernel_launch(void* const* d_in, const int* in_sizes, int n_in,
                              void* d_out, int out_size) {
    const float* Y   = (const float*)d_in[0];
    const float* inW = (const float*)d_in[1];
    float* out = (float*)d_out;

    k_init<<<(VOL + 255) / 256, 256>>>(Y, 0.1f);

    double mu1d = 0.1, mu2d = 0.1, mu2pd = 0.0;
    const double lam = 0.1;

    for (int it = 0; it < 20; it++) {
        float mu1 = (float)mu1d, mu2 = (float)mu2d, mu2p = (float)mu2pd;
        float mu1n = (float)(mu1d * 1.05);
        float inv_mu2 = (float)(1.0 / mu2d);
        float thr = (float)(lam / mu2d);
        int pp = it & 1;

        k_cfwd_rows<<<NB*128, 256>>>(pp, mu2, mu2p, inv_mu2, thr);
        k_ccols<<<NB*NK*8, 512>>>(mu1, mu2);
        k_irows_cinv<<<NB*128, 512>>>(Y, inW, mu1, mu1n, (it == 19) ? out : nullptr);

        mu2pd = mu2d;
        mu1d *= 1.05;
        mu2d *= 1.05;
    }
}

// round 13
// speedup vs baseline: 1.1801x; 1.0217x over previous
#include <cuda_runtime.h>
#include <math.h>

#define NB 4
#define NC 31
#define NK 16                 // Hermitian half of C-spectrum
#define SLICE 16384           // 128*128
#define VOL   (NB*NC*SLICE)   // 2031616

// ---------------- static scratch --------------------------------------------
__device__ float  g_Z[VOL];
__device__ float  g_M[VOL];       // M = mu1*X + G1
__device__ float  g_G1[VOL];
__device__ float  g_Ph[2][VOL];
__device__ float  g_Pv[2][VOL];
__device__ float  g_Ps[VOL];
__device__ float2 g_S[NB*NK*SLICE];   // spectral working buffer

// ---------------- helpers ---------------------------------------------------
__device__ __forceinline__ float shrinkf(float x, float t) {
    return copysignf(fmaxf(fabsf(x) - t, 0.0f), x);
}
__device__ __forceinline__ float2 cadd(float2 a, float2 b){ return make_float2(a.x+b.x, a.y+b.y); }
__device__ __forceinline__ float2 csub(float2 a, float2 b){ return make_float2(a.x-b.x, a.y-b.y); }
__device__ __forceinline__ float2 cmuln(float2 d, float2 w){   // d * (wx - i*wy)
    return make_float2(d.x*w.x + d.y*w.y, d.y*w.x - d.x*w.y);
}
__device__ __forceinline__ float2 cmulp(float2 d, float2 w){   // d * (wx + i*wy)
    return make_float2(d.x*w.x - d.y*w.y, d.x*w.y + d.y*w.x);
}
__device__ __forceinline__ float2 shfl2(float2 v, int m){
    float2 r;
    r.x = __shfl_xor_sync(0xffffffffu, v.x, m);
    r.y = __shfl_xor_sync(0xffffffffu, v.y, m);
    return r;
}
// flat [c][k] table: twck[c*NK+k] = (cos, -sin)(2*pi*k*c/31)
__device__ __forceinline__ void build_twck(float2* twck, int tid, int nthr){
    for (int e = tid; e < NC*NK; e += nthr){
        int c = e >> 4, k = e & 15;
        int m = (k * c) % NC;
        float s, co; sincospif((float)m * (2.f/31.f), &s, &co);
        twck[e] = make_float2(co, -s);
    }
}

// ---------------- warp-level 128-pt FFT (4 complex per lane) -----------------
__device__ __forceinline__ void wfft_fwd(float2 v[4], const float2* __restrict__ twd, int t){
    {   // hs=6
        float2 w0 = twd[t], w1 = twd[32 + t];
        float2 a = v[0], b = v[2]; v[0] = cadd(a,b); v[2] = cmuln(csub(a,b), w0);
        a = v[1]; b = v[3]; v[1] = cadd(a,b); v[3] = cmuln(csub(a,b), w1);
    }
    {   // hs=5
        float2 w = twd[2*t];
        float2 a = v[0], b = v[1]; v[0] = cadd(a,b); v[1] = cmuln(csub(a,b), w);
        a = v[2]; b = v[3]; v[2] = cadd(a,b); v[3] = cmuln(csub(a,b), w);
    }
    #pragma unroll
    for (int hs = 4; hs >= 0; hs--){
        int half = 1 << hs;
        float2 w = twd[(t & (half-1)) << (6 - hs)];
        bool up = (t & half) != 0;
        #pragma unroll
        for (int j = 0; j < 4; j++){
            float2 pv = shfl2(v[j], half);
            v[j] = up ? cmuln(csub(pv, v[j]), w) : cadd(v[j], pv);
        }
    }
}

__device__ __forceinline__ void wfft_inv(float2 v[4], const float2* __restrict__ twd, int t){
    #pragma unroll
    for (int hs = 0; hs <= 4; hs++){
        int half = 1 << hs;
        float2 w = twd[(t & (half-1)) << (6 - hs)];
        bool up = (t & half) != 0;
        #pragma unroll
        for (int j = 0; j < 4; j++){
            float2 u = up ? cmulp(v[j], w) : v[j];
            float2 pu = shfl2(u, half);
            v[j] = up ? csub(pu, u) : cadd(u, pu);
        }
    }
    {   // hs=5
        float2 w = twd[2*t];
        float2 tm = cmulp(v[1], w); float2 x0 = v[0]; v[0] = cadd(x0,tm); v[1] = csub(x0,tm);
        tm = cmulp(v[3], w); x0 = v[2]; v[2] = cadd(x0,tm); v[3] = csub(x0,tm);
    }
    {   // hs=6
        float2 w0 = twd[t], w1 = twd[32 + t];
        float2 tm = cmulp(v[2], w0); float2 x0 = v[0]; v[0] = cadd(x0,tm); v[2] = csub(x0,tm);
        tm = cmulp(v[3], w1); x0 = v[1]; v[1] = cadd(x0,tm); v[3] = csub(x0,tm);
    }
}

// ---------------- init ------------------------------------------------------
__global__ void k_init(const float* __restrict__ Y, float mu1_0) {
    int i = blockIdx.x * blockDim.x + threadIdx.x;
    if (i >= VOL) return;
    float y = Y[i];
    g_Z[i] = y;
    g_M[i] = mu1_0 * y;
    g_G1[i] = 0.f;
    g_Ph[0][i] = 0.f; g_Pv[0][i] = 0.f; g_Ps[i] = 0.f;
}

// ---------------- fused: pencil phase + real C-DFT + forward row FFT --------
// 2 threads per pencil (c-range split), 128 pencils per block, 512 blocks.
// Phase 2 uses c<->31-c symmetry: fold nu into even/odd sums, 15 c-steps.
__global__ __launch_bounds__(256, 4) void k_cfwd_rows(int pp, float mu2,
                                                      float mu2p, float inv_mu2, float thr)
{
    __shared__ float2 twck[NC*NK];
    __shared__ float2 twd[64];
    __shared__ float  buf[NK*128*2];    // 16KB union: numer[31*128] | sF[16*128] float2
    float*  numer = buf;
    float2* sF    = (float2*)buf;

    int tid = threadIdx.x;
    build_twck(twck, tid, 256);
    if (tid < 64){ float s, c; sincospif((float)tid*(1.f/64.f), &s, &c); twd[tid] = make_float2(c, s); }

    int pl = tid & 127;        // pencil within block (== w)
    int q  = tid >> 7;         // c-range half: 0 -> [0,16), 1 -> [16,31)
    int n  = blockIdx.x >> 7;
    int h  = blockIdx.x & 127;
    int w  = pl;

    int ow1 = ((w + 1)   & 127) - w;
    int owm = ((w + 127) & 127) - w;
    int oh1 = ((((h + 1)   & 127) - h) << 7);
    int ohm = ((((h + 127) & 127) - h) << 7);
    int base = n * (NC * SLICE) + (h << 7) + w;

    const float* __restrict__ Ph_in  = g_Ph[pp];
    float*       __restrict__ Ph_out = g_Ph[pp ^ 1];
    const float* __restrict__ Pv_in  = g_Pv[pp];
    float*       __restrict__ Pv_out = g_Pv[pp ^ 1];

    int c_lo  = q ? 16 : 0;
    int c_hi  = q ? 31 : 16;
    int cprev = q ? 15 : 30;

    // boundary pre-reads: must complete before the other half writes g_Ps
    float z_lo = g_Z[base + c_lo * SLICE];
    float zp   = g_Z[base + cprev * SLICE];
    float Psp  = g_Ps[base + cprev * SLICE];
    __syncthreads();   // tables ready AND boundary reads ordered before loop writes

    float As_prev;
    {
        float d  = zp - z_lo;
        float g2 = Psp - mu2p * d;
        float qq = g2 * inv_mu2;
        As_prev  = shrinkf(d - qq, thr) + qq;
    }

    // ---- phase 1: pencil math for this thread's c-range ----
    float zc = z_lo;
    for (int c = c_lo; c < c_hi; c++) {
        int i = base + c * SLICE;
        int cn = (c == 30) ? 0 : c + 1;
        float znext = g_Z[base + cn * SLICE];
        float zw1 = g_Z[i + ow1], zwm = g_Z[i + owm];
        float zh1 = g_Z[i + oh1], zhm = g_Z[i + ohm];

        float dh  = zc - zw1;
        float g2h = Ph_in[i] - mu2p * dh;
        float qh  = g2h * inv_mu2;
        float Ah  = shrinkf(dh - qh, thr) + qh;
        Ph_out[i] = mu2 * Ah;
        float dhm  = zwm - zc;
        float g2hm = Ph_in[i + owm] - mu2p * dhm;
        float qhm  = g2hm * inv_mu2;
        float Ahm  = shrinkf(dhm - qhm, thr) + qhm;

        float dv  = zc - zh1;
        float g2v = Pv_in[i] - mu2p * dv;
        float qv  = g2v * inv_mu2;
        float Av  = shrinkf(dv - qv, thr) + qv;
        Pv_out[i] = mu2 * Av;
        float dvm  = zhm - zc;
        float g2vm = Pv_in[i + ohm] - mu2p * dvm;
        float qvm  = g2vm * inv_mu2;
        float Avm  = shrinkf(dvm - qvm, thr) + qvm;

        float ds  = zc - znext;
        float g2s = g_Ps[i] - mu2p * ds;
        float qs  = g2s * inv_mu2;
        float As  = shrinkf(ds - qs, thr) + qs;
        g_Ps[i]   = mu2 * As;

        numer[c * 128 + pl] = g_M[i]
                    + mu2 * ((Ah - Ahm) + (Av - Avm) + (As - As_prev));
        As_prev = As;
        zc = znext;
    }
    __syncthreads();

    // ---- phase 2: real 31-pt DFT with c<->31-c folding ----
    // F[k].x = nu0 + sum_{c=1..15} (nu_c + nu_{31-c}) * cos(2*pi*k*c/31)
    // F[k].y =       sum_{c=1..15} (nu_c - nu_{31-c}) * (-sin(2*pi*k*c/31))
    float nu0 = numer[pl];
    float2 F[8];
    #pragma unroll
    for (int kk = 0; kk < 8; kk++) F[kk] = make_float2(nu0, 0.f);
    int k0 = q << 3;
    for (int c = 1; c <= 15; c++) {
        float na = numer[c * 128 + pl];
        float nb = numer[(31 - c) * 128 + pl];
        float e = na + nb, o = na - nb;
        const float2* tc = twck + (c << 4) + k0;
        #pragma unroll
        for (int kk = 0; kk < 8; kk++) {
            float2 t = tc[kk];
            F[kk].x = fmaf(e, t.x, F[kk].x);
            F[kk].y = fmaf(o, t.y, F[kk].y);
        }
    }
    __syncthreads();   // all numer reads done before sF overwrites the buffer

    #pragma unroll
    for (int kk = 0; kk < 8; kk++) sF[(k0 + kk)*128 + pl] = F[kk];
    __syncthreads();

    // ---- phase 3: forward row FFT: 16 k-tasks, 8 warps (2 each) ----
    int wid = tid >> 5, t = tid & 31;
    #pragma unroll
    for (int ki = 0; ki < 2; ki++){
        int k = wid + ki * 8;
        float2 v[4];
        #pragma unroll
        for (int j = 0; j < 4; j++) v[j] = sF[k*128 + t + 32*j];
        wfft_fwd(v, twd, t);
        float2* dst = g_S + (size_t)(n*NK + k)*SLICE + (h << 7);
        #pragma unroll
        for (int j = 0; j < 4; j++) dst[t + 32*j] = v[j];
    }
}

// ---------------- fused: col fwd FFT + spectral divide + col inv FFT --------
__global__ __launch_bounds__(512) void k_ccols(float mu1, float mu2){
    __shared__ float2 twd[64];
    __shared__ float  d128s[128];   // 2-2cos(2*pi*brev(pos)/128), by POSITION
    __shared__ float2 sT[16*129];
    int tid = threadIdx.x;
    if (tid < 64){ float s, c; sincospif((float)tid*(1.f/64.f), &s, &c); twd[tid] = make_float2(c, s); }
    if (tid >= 64 && tid < 192){
        int e = tid - 64;
        int f = __brev((unsigned)e) >> 25;
        d128s[e] = 2.f - 2.f * cospif((float)f * (1.f/64.f));
    }

    int s  = blockIdx.x >> 3;
    int w0 = (blockIdx.x & 7) << 4;
    int kc = s & (NK - 1);
    float dck = 2.f - 2.f * cospif((float)kc * (2.f/31.f));

    const float2* src = g_S + (size_t)s * SLICE + w0;
    #pragma unroll
    for (int st = 0; st < 4; st++){
        int idx = tid + st * 512;
        int h = idx >> 4, wl = idx & 15;
        sT[wl*129 + h] = src[h*128 + wl];
    }
    __syncthreads();

    int wid = tid >> 5, t = tid & 31;
    {
        int wl = wid;
        float2 v[4];
        #pragma unroll
        for (int j = 0; j < 4; j++) v[j] = sT[wl*129 + t + 32*j];
        wfft_fwd(v, twd, t);
        float dw = d128s[w0 + wl];
        #pragma unroll
        for (int j = 0; j < 4; j++){
            float sc = __fdividef(6.103515625e-05f,      // 1/16384
                                  mu1 + mu2 * (dck + d128s[t + 32*j] + dw));
            v[j].x *= sc; v[j].y *= sc;
        }
        wfft_inv(v, twd, t);
        #pragma unroll
        for (int j = 0; j < 4; j++) sT[wl*129 + t + 32*j] = v[j];
    }
    __syncthreads();

    float2* dst = g_S + (size_t)s * SLICE + w0;
    #pragma unroll
    for (int st = 0; st < 4; st++){
        int idx = tid + st * 512;
        int h = idx >> 4, wl = idx & 15;
        dst[h*128 + wl] = sT[wl*129 + h];
    }
}

// ---------------- Hermitian pair synthesis (c and 31-c share twiddles) ------
template<bool FINAL>
__device__ __forceinline__ void csynth_pairs(
    const float2* __restrict__ twck,
    float H0, const float* Hx, const float* Hy,
    int cg, int base, float mu1, float mu1n,
    const float* __restrict__ Y, const float* __restrict__ inW,
    float* __restrict__ out)
{
    #pragma unroll
    for (int j = 0; j < 4; j++) {
        int tk = cg + (j << 2);   // task 0..15; warp-uniform (cg uniform per warp)
        if (tk == 0) {
            float acc = H0;
            #pragma unroll
            for (int k = 1; k < NK; k++) acc += Hx[k-1];
            int i = base;   // c = 0
            if (FINAL) {
                out[i] = acc;
            } else {
                g_Z[i] = acc;
                float xw = inW[i], y = Y[i], g1 = g_G1[i];
                float x = __fdividef(fmaf(xw, y, fmaf(mu1, acc, -g1)), xw + mu1);
                float g1n = fmaf(mu1, x - acc, g1);
                g_G1[i] = g1n;
                g_M[i]  = fmaf(mu1n, x, g1n);
            }
        } else {
            const float2* tc = twck + (tk << 4);
            float sx = 0.f, sy = 0.f;
            #pragma unroll
            for (int k = 1; k < NK; k++) {
                float2 tt = tc[k];
                sx = fmaf(Hx[k-1], tt.x, sx);
                sy = fmaf(Hy[k-1], tt.y, sy);
            }
            float accA = H0 + sx + sy;       // c = tk
            float accB = H0 + sx - sy;       // c = 31 - tk
            int iA = base + tk * SLICE;
            int iB = base + (31 - tk) * SLICE;
            if (FINAL) {
                out[iA] = accA;
                out[iB] = accB;
            } else {
                g_Z[iA] = accA;
                {
                    float xw = inW[iA], y = Y[iA], g1 = g_G1[iA];
                    float x = __fdividef(fmaf(xw, y, fmaf(mu1, accA, -g1)), xw + mu1);
                    float g1n = fmaf(mu1, x - accA, g1);
                    g_G1[iA] = g1n;
                    g_M[iA]  = fmaf(mu1n, x, g1n);
                }
                g_Z[iB] = accB;
                {
                    float xw = inW[iB], y = Y[iB], g1 = g_G1[iB];
                    float x = __fdividef(fmaf(xw, y, fmaf(mu1, accB, -g1)), xw + mu1);
                    float g1n = fmaf(mu1, x - accB, g1);
                    g_G1[iB] = g1n;
                    g_M[iB]  = fmaf(mu1n, x, g1n);
                }
            }
        }
    }
}

// ---------------- fused: inverse row FFT + Hermitian C-synthesis + update ---
__global__ __launch_bounds__(512, 2) void k_irows_cinv(const float* __restrict__ Y,
                                                       const float* __restrict__ inW,
                                                       float mu1, float mu1n,
                                                       float* __restrict__ out)
{
    __shared__ float2 twd[64];
    __shared__ float2 twck[NC*NK];
    __shared__ float2 sH[NK*128];
    int tid = threadIdx.x;
    if (tid < 64){ float s, c; sincospif((float)tid*(1.f/64.f), &s, &c); twd[tid] = make_float2(c, s); }
    build_twck(twck, tid, 512);
    __syncthreads();

    int n = blockIdx.x >> 7, h = blockIdx.x & 127;
    int wid = tid >> 5, t = tid & 31;
    {
        const float2* src = g_S + (size_t)(n*NK + wid)*SLICE + h*128;
        float2 v[4];
        #pragma unroll
        for (int j = 0; j < 4; j++) v[j] = src[t + 32*j];
        wfft_inv(v, twd, t);
        #pragma unroll
        for (int j = 0; j < 4; j++) sH[wid*128 + t + 32*j] = v[j];
    }
    __syncthreads();

    int w = tid & 127, cg = tid >> 7;   // 4 task-groups per pencil
    float H0;
    float Hx[NK-1], Hy[NK-1];
    const float i31 = 1.f/31.f, i31x2 = 2.f/31.f;
    H0 = sH[w].x * i31;
    #pragma unroll
    for (int k = 1; k < NK; k++){
        float2 v = sH[k*128 + w];
        Hx[k-1] = v.x * i31x2; Hy[k-1] = v.y * i31x2;
    }

    int base = n * (NC * SLICE) + h*128 + w;
    if (out != nullptr)
        csynth_pairs<true >(twck, H0, Hx, Hy, cg, base, mu1, mu1n, Y, inW, out);
    else
        csynth_pairs<false>(twck, H0, Hx, Hy, cg, base, mu1, mu1n, Y, inW, out);
}

// ---------------- launch ----------------------------------------------------
extern "C" void kernel_launch(void* const* d_in, const int* in_sizes, int n_in,
                              void* d_out, int out_size) {
    const float* Y   = (const float*)d_in[0];
    const float* inW = (const float*)d_in[1];
    float* out = (float*)d_out;

    k_init<<<(VOL + 255) / 256, 256>>>(Y, 0.1f);

    double mu1d = 0.1, mu2d = 0.1, mu2pd = 0.0;
    const double lam = 0.1;

    for (int it = 0; it < 20; it++) {
        float mu1 = (float)mu1d, mu2 = (float)mu2d, mu2p = (float)mu2pd;
        float mu1n = (float)(mu1d * 1.05);
        float inv_mu2 = (float)(1.0 / mu2d);
        float thr = (float)(lam / mu2d);
        int pp = it & 1;

        k_cfwd_rows<<<NB*128, 256>>>(pp, mu2, mu2p, inv_mu2, thr);
        k_ccols<<<NB*NK*8, 512>>>(mu1, mu2);
        k_irows_cinv<<<NB*128, 512>>>(Y, inW, mu1, mu1n, (it == 19) ? out : nullptr);

        mu2pd = mu2d;
        mu1d *= 1.05;
        mu2d *= 1.05;
    }
}

// round 14
// speedup vs baseline: 1.4954x; 1.2672x over previous
#include <cuda_runtime.h>
#include <math.h>

#define NB 4
#define NC 31
#define NK 16                 // Hermitian half of C-spectrum
#define SLICE 16384           // 128*128
#define VOL   (NB*NC*SLICE)   // 2031616

// ---------------- static scratch (no init kernel needed) --------------------
__device__ float  g_Z[VOL];
__device__ float2 g_GM[VOL];        // .x = G1, .y = M = mu1*X + G1
__device__ float2 g_Phv[2][VOL];    // .x = Ph, .y = Pv (ping-pong)
__device__ float  g_Ps[VOL];
__device__ float2 g_S[NB*NK*SLICE]; // spectral working buffer

// ---------------- helpers ---------------------------------------------------
__device__ __forceinline__ float shrinkf(float x, float t) {
    return copysignf(fmaxf(fabsf(x) - t, 0.0f), x);
}
__device__ __forceinline__ float2 cadd(float2 a, float2 b){ return make_float2(a.x+b.x, a.y+b.y); }
__device__ __forceinline__ float2 csub(float2 a, float2 b){ return make_float2(a.x-b.x, a.y-b.y); }
__device__ __forceinline__ float2 cmuln(float2 d, float2 w){   // d * (wx - i*wy)
    return make_float2(d.x*w.x + d.y*w.y, d.y*w.x - d.x*w.y);
}
__device__ __forceinline__ float2 cmulp(float2 d, float2 w){   // d * (wx + i*wy)
    return make_float2(d.x*w.x - d.y*w.y, d.x*w.y + d.y*w.x);
}
__device__ __forceinline__ float2 shfl2(float2 v, int m){
    float2 r;
    r.x = __shfl_xor_sync(0xffffffffu, v.x, m);
    r.y = __shfl_xor_sync(0xffffffffu, v.y, m);
    return r;
}
// flat [c][k] table: twck[c*NK+k] = (cos, -sin)(2*pi*k*c/31)
__device__ __forceinline__ void build_twck(float2* twck, int tid, int nthr){
    for (int e = tid; e < NC*NK; e += nthr){
        int c = e >> 4, k = e & 15;
        int m = (k * c) % NC;
        float s, co; sincospif((float)m * (2.f/31.f), &s, &co);
        twck[e] = make_float2(co, -s);
    }
}

// ---------------- warp-level 128-pt FFT (4 complex per lane) -----------------
__device__ __forceinline__ void wfft_fwd(float2 v[4], const float2* __restrict__ twd, int t){
    {   // hs=6
        float2 w0 = twd[t], w1 = twd[32 + t];
        float2 a = v[0], b = v[2]; v[0] = cadd(a,b); v[2] = cmuln(csub(a,b), w0);
        a = v[1]; b = v[3]; v[1] = cadd(a,b); v[3] = cmuln(csub(a,b), w1);
    }
    {   // hs=5
        float2 w = twd[2*t];
        float2 a = v[0], b = v[1]; v[0] = cadd(a,b); v[1] = cmuln(csub(a,b), w);
        a = v[2]; b = v[3]; v[2] = cadd(a,b); v[3] = cmuln(csub(a,b), w);
    }
    #pragma unroll
    for (int hs = 4; hs >= 0; hs--){
        int half = 1 << hs;
        float2 w = twd[(t & (half-1)) << (6 - hs)];
        bool up = (t & half) != 0;
        #pragma unroll
        for (int j = 0; j < 4; j++){
            float2 pv = shfl2(v[j], half);
            v[j] = up ? cmuln(csub(pv, v[j]), w) : cadd(v[j], pv);
        }
    }
}

__device__ __forceinline__ void wfft_inv(float2 v[4], const float2* __restrict__ twd, int t){
    #pragma unroll
    for (int hs = 0; hs <= 4; hs++){
        int half = 1 << hs;
        float2 w = twd[(t & (half-1)) << (6 - hs)];
        bool up = (t & half) != 0;
        #pragma unroll
        for (int j = 0; j < 4; j++){
            float2 u = up ? cmulp(v[j], w) : v[j];
            float2 pu = shfl2(u, half);
            v[j] = up ? csub(pu, u) : cadd(u, pu);
        }
    }
    {   // hs=5
        float2 w = twd[2*t];
        float2 tm = cmulp(v[1], w); float2 x0 = v[0]; v[0] = cadd(x0,tm); v[1] = csub(x0,tm);
        tm = cmulp(v[3], w); x0 = v[2]; v[2] = cadd(x0,tm); v[3] = csub(x0,tm);
    }
    {   // hs=6
        float2 w0 = twd[t], w1 = twd[32 + t];
        float2 tm = cmulp(v[2], w0); float2 x0 = v[0]; v[0] = cadd(x0,tm); v[2] = csub(x0,tm);
        tm = cmulp(v[3], w1); x0 = v[1]; v[1] = cadd(x0,tm); v[3] = csub(x0,tm);
    }
}

// ---------------- fused: pencil phase + real C-DFT + forward row FFT --------
// 2 threads per pencil (c-range split), 128 pencils per block, 512 blocks.
// FIRST: iteration 0 — Z comes from Y, P*/M implicit (0 / mu1*Y); no init kernel.
template<bool FIRST>
__global__ __launch_bounds__(256, 4) void k_cfwd_rows(const float* __restrict__ Y,
                                                      int pp, float mu1, float mu2,
                                                      float mu2p, float inv_mu2, float thr)
{
    __shared__ float2 twck[NC*NK];
    __shared__ float2 twd[64];
    __shared__ float  buf[NK*128*2];    // 16KB union: numer[31*128] | sF[16*128] float2
    float*  numer = buf;
    float2* sF    = (float2*)buf;

    int tid = threadIdx.x;
    build_twck(twck, tid, 256);
    if (tid < 64){ float s, c; sincospif((float)tid*(1.f/64.f), &s, &c); twd[tid] = make_float2(c, s); }

    int pl = tid & 127;        // pencil within block (== w)
    int q  = tid >> 7;         // c-range half: 0 -> [0,16), 1 -> [16,31)
    int n  = blockIdx.x >> 7;
    int h  = blockIdx.x & 127;
    int w  = pl;

    int ow1 = ((w + 1)   & 127) - w;
    int owm = ((w + 127) & 127) - w;
    int oh1 = ((((h + 1)   & 127) - h) << 7);
    int ohm = ((((h + 127) & 127) - h) << 7);
    int base = n * (NC * SLICE) + (h << 7) + w;

    const float*  __restrict__ Zs      = FIRST ? Y : g_Z;
    const float2* __restrict__ Phv_in  = g_Phv[pp];
    float2*       __restrict__ Phv_out = g_Phv[pp ^ 1];

    int c_lo  = q ? 16 : 0;
    int c_hi  = q ? 31 : 16;
    int cprev = q ? 15 : 30;

    // boundary pre-reads: must complete before the other half writes g_Ps
    float z_lo = Zs[base + c_lo * SLICE];
    float zp   = Zs[base + cprev * SLICE];
    float Psp  = FIRST ? 0.f : g_Ps[base + cprev * SLICE];
    __syncthreads();   // tables ready AND boundary reads ordered before loop writes

    float As_prev;
    {
        float d  = zp - z_lo;
        float g2 = Psp - mu2p * d;
        float qq = g2 * inv_mu2;
        As_prev  = shrinkf(d - qq, thr) + qq;
    }

    // ---- phase 1: pencil math for this thread's c-range ----
    float zc = z_lo;
    for (int c = c_lo; c < c_hi; c++) {
        int i = base + c * SLICE;
        int cn = (c == 30) ? 0 : c + 1;
        float znext = Zs[base + cn * SLICE];
        float zw1 = Zs[i + ow1], zwm = Zs[i + owm];
        float zh1 = Zs[i + oh1], zhm = Zs[i + ohm];

        float2 phv  = FIRST ? make_float2(0.f, 0.f) : Phv_in[i];
        float  phm  = FIRST ? 0.f : Phv_in[i + owm].x;
        float  pvm  = FIRST ? 0.f : Phv_in[i + ohm].y;
        float  psc  = FIRST ? 0.f : g_Ps[i];
        float  Mi   = FIRST ? (mu1 * zc) : g_GM[i].y;

        float dh  = zc - zw1;
        float g2h = phv.x - mu2p * dh;
        float qh  = g2h * inv_mu2;
        float Ah  = shrinkf(dh - qh, thr) + qh;
        float dhm  = zwm - zc;
        float g2hm = phm - mu2p * dhm;
        float qhm  = g2hm * inv_mu2;
        float Ahm  = shrinkf(dhm - qhm, thr) + qhm;

        float dv  = zc - zh1;
        float g2v = phv.y - mu2p * dv;
        float qv  = g2v * inv_mu2;
        float Av  = shrinkf(dv - qv, thr) + qv;
        float dvm  = zhm - zc;
        float g2vm = pvm - mu2p * dvm;
        float qvm  = g2vm * inv_mu2;
        float Avm  = shrinkf(dvm - qvm, thr) + qvm;

        Phv_out[i] = make_float2(mu2 * Ah, mu2 * Av);

        float ds  = zc - znext;
        float g2s = psc - mu2p * ds;
        float qs  = g2s * inv_mu2;
        float As  = shrinkf(ds - qs, thr) + qs;
        g_Ps[i]   = mu2 * As;

        numer[c * 128 + pl] = Mi
                    + mu2 * ((Ah - Ahm) + (Av - Avm) + (As - As_prev));
        As_prev = As;
        zc = znext;
    }
    __syncthreads();

    // ---- phase 2: real 31-pt DFT with c<->31-c folding ----
    float nu0 = numer[pl];
    float2 F[8];
    #pragma unroll
    for (int kk = 0; kk < 8; kk++) F[kk] = make_float2(nu0, 0.f);
    int k0 = q << 3;
    for (int c = 1; c <= 15; c++) {
        float na = numer[c * 128 + pl];
        float nb = numer[(31 - c) * 128 + pl];
        float e = na + nb, o = na - nb;
        const float2* tc = twck + (c << 4) + k0;
        #pragma unroll
        for (int kk = 0; kk < 8; kk++) {
            float2 t = tc[kk];
            F[kk].x = fmaf(e, t.x, F[kk].x);
            F[kk].y = fmaf(o, t.y, F[kk].y);
        }
    }
    __syncthreads();   // all numer reads done before sF overwrites the buffer

    #pragma unroll
    for (int kk = 0; kk < 8; kk++) sF[(k0 + kk)*128 + pl] = F[kk];
    __syncthreads();

    // ---- phase 3: forward row FFT: 16 k-tasks, 8 warps (2 each) ----
    int wid = tid >> 5, t = tid & 31;
    #pragma unroll
    for (int ki = 0; ki < 2; ki++){
        int k = wid + ki * 8;
        float2 v[4];
        #pragma unroll
        for (int j = 0; j < 4; j++) v[j] = sF[k*128 + t + 32*j];
        wfft_fwd(v, twd, t);
        float2* dst = g_S + (size_t)(n*NK + k)*SLICE + (h << 7);
        #pragma unroll
        for (int j = 0; j < 4; j++) dst[t + 32*j] = v[j];
    }
}

// ---------------- fused: col fwd FFT + spectral divide + col inv FFT --------
__global__ __launch_bounds__(512) void k_ccols(float mu1, float mu2){
    __shared__ float2 twd[64];
    __shared__ float  d128s[128];   // 2-2cos(2*pi*brev(pos)/128), by POSITION
    __shared__ float2 sT[16*129];
    int tid = threadIdx.x;
    if (tid < 64){ float s, c; sincospif((float)tid*(1.f/64.f), &s, &c); twd[tid] = make_float2(c, s); }
    if (tid >= 64 && tid < 192){
        int e = tid - 64;
        int f = __brev((unsigned)e) >> 25;
        d128s[e] = 2.f - 2.f * cospif((float)f * (1.f/64.f));
    }

    int s  = blockIdx.x >> 3;
    int w0 = (blockIdx.x & 7) << 4;
    int kc = s & (NK - 1);
    float dck = 2.f - 2.f * cospif((float)kc * (2.f/31.f));

    const float2* src = g_S + (size_t)s * SLICE + w0;
    #pragma unroll
    for (int st = 0; st < 4; st++){
        int idx = tid + st * 512;
        int h = idx >> 4, wl = idx & 15;
        sT[wl*129 + h] = src[h*128 + wl];
    }
    __syncthreads();

    int wid = tid >> 5, t = tid & 31;
    {
        int wl = wid;
        float2 v[4];
        #pragma unroll
        for (int j = 0; j < 4; j++) v[j] = sT[wl*129 + t + 32*j];
        wfft_fwd(v, twd, t);
        float dw = d128s[w0 + wl];
        #pragma unroll
        for (int j = 0; j < 4; j++){
            float sc = __fdividef(6.103515625e-05f,      // 1/16384
                                  mu1 + mu2 * (dck + d128s[t + 32*j] + dw));
            v[j].x *= sc; v[j].y *= sc;
        }
        wfft_inv(v, twd, t);
        #pragma unroll
        for (int j = 0; j < 4; j++) sT[wl*129 + t + 32*j] = v[j];
    }
    __syncthreads();

    float2* dst = g_S + (size_t)s * SLICE + w0;
    #pragma unroll
    for (int st = 0; st < 4; st++){
        int idx = tid + st * 512;
        int h = idx >> 4, wl = idx & 15;
        dst[h*128 + wl] = sT[wl*129 + h];
    }
}

// ---------------- Hermitian pair synthesis epilogue -------------------------
// MODE: 0 = FIRST (G1 = 0, skip GM load), 1 = MID, 2 = FINAL (write out only)
template<int MODE>
__device__ __forceinline__ void upd_point(int i, float acc, float mu1, float mu1n,
                                          const float* __restrict__ Y,
                                          const float* __restrict__ inW,
                                          float* __restrict__ out)
{
    if (MODE == 2) {
        out[i] = acc;
    } else {
        g_Z[i] = acc;
        float xw = inW[i], y = Y[i];
        float g1 = (MODE == 0) ? 0.f : g_GM[i].x;
        float x = __fdividef(fmaf(xw, y, fmaf(mu1, acc, -g1)), xw + mu1);
        float g1n = fmaf(mu1, x - acc, g1);
        g_GM[i] = make_float2(g1n, fmaf(mu1n, x, g1n));
    }
}

template<int MODE>
__device__ __forceinline__ void csynth_pairs(
    const float2* __restrict__ twck,
    float H0, const float* Hx, const float* Hy,
    int cg, int base, float mu1, float mu1n,
    const float* __restrict__ Y, const float* __restrict__ inW,
    float* __restrict__ out)
{
    #pragma unroll
    for (int j = 0; j < 4; j++) {
        int tk = cg + (j << 2);   // task 0..15; warp-uniform (cg uniform per warp)
        if (tk == 0) {
            float acc = H0;
            #pragma unroll
            for (int k = 1; k < NK; k++) acc += Hx[k-1];
            upd_point<MODE>(base, acc, mu1, mu1n, Y, inW, out);   // c = 0
        } else {
            const float2* tc = twck + (tk << 4);
            float sx = 0.f, sy = 0.f;
            #pragma unroll
            for (int k = 1; k < NK; k++) {
                float2 tt = tc[k];
                sx = fmaf(Hx[k-1], tt.x, sx);
                sy = fmaf(Hy[k-1], tt.y, sy);
            }
            upd_point<MODE>(base + tk * SLICE,        H0 + sx + sy, mu1, mu1n, Y, inW, out);
            upd_point<MODE>(base + (31 - tk) * SLICE, H0 + sx - sy, mu1, mu1n, Y, inW, out);
        }
    }
}

// ---------------- fused: inverse row FFT + Hermitian C-synthesis + update ---
template<int MODE>
__global__ __launch_bounds__(512, 2) void k_irows_cinv(const float* __restrict__ Y,
                                                       const float* __restrict__ inW,
                                                       float mu1, float mu1n,
                                                       float* __restrict__ out)
{
    __shared__ float2 twd[64];
    __shared__ float2 twck[NC*NK];
    __shared__ float2 sH[NK*128];
    int tid = threadIdx.x;
    if (tid < 64){ float s, c; sincospif((float)tid*(1.f/64.f), &s, &c); twd[tid] = make_float2(c, s); }
    build_twck(twck, tid, 512);
    __syncthreads();

    int n = blockIdx.x >> 7, h = blockIdx.x & 127;
    int wid = tid >> 5, t = tid & 31;
    {
        const float2* src = g_S + (size_t)(n*NK + wid)*SLICE + h*128;
        float2 v[4];
        #pragma unroll
        for (int j = 0; j < 4; j++) v[j] = src[t + 32*j];
        wfft_inv(v, twd, t);
        #pragma unroll
        for (int j = 0; j < 4; j++) sH[wid*128 + t + 32*j] = v[j];
    }
    __syncthreads();

    int w = tid & 127, cg = tid >> 7;   // 4 task-groups per pencil
    float H0;
    float Hx[NK-1], Hy[NK-1];
    const float i31 = 1.f/31.f, i31x2 = 2.f/31.f;
    H0 = sH[w].x * i31;
    #pragma unroll
    for (int k = 1; k < NK; k++){
        float2 v = sH[k*128 + w];
        Hx[k-1] = v.x * i31x2; Hy[k-1] = v.y * i31x2;
    }

    int base = n * (NC * SLICE) + h*128 + w;
    csynth_pairs<MODE>(twck, H0, Hx, Hy, cg, base, mu1, mu1n, Y, inW, out);
}

// ---------------- launch ----------------------------------------------------
extern "C" void kernel_launch(void* const* d_in, const int* in_sizes, int n_in,
                              void* d_out, int out_size) {
    const float* Y   = (const float*)d_in[0];
    const float* inW = (const float*)d_in[1];
    float* out = (float*)d_out;

    double mu1d = 0.1, mu2d = 0.1, mu2pd = 0.0;
    const double lam = 0.1;

    for (int it = 0; it < 20; it++) {
        float mu1 = (float)mu1d, mu2 = (float)mu2d, mu2p = (float)mu2pd;
        float mu1n = (float)(mu1d * 1.05);
        float inv_mu2 = (float)(1.0 / mu2d);
        float thr = (float)(lam / mu2d);
        int pp = it & 1;

        if (it == 0)
            k_cfwd_rows<true ><<<NB*128, 256>>>(Y, pp, mu1, mu2, mu2p, inv_mu2, thr);
        else
            k_cfwd_rows<false><<<NB*128, 256>>>(Y, pp, mu1, mu2, mu2p, inv_mu2, thr);

        k_ccols<<<NB*NK*8, 512>>>(mu1, mu2);

        if (it == 0)
            k_irows_cinv<0><<<NB*128, 512>>>(Y, inW, mu1, mu1n, out);
        else if (it == 19)
            k_irows_cinv<2><<<NB*128, 512>>>(Y, inW, mu1, mu1n, out);
        else
            k_irows_cinv<1><<<NB*128, 512>>>(Y, inW, mu1, mu1n, out);

        mu2pd = mu2d;
        mu1d *= 1.05;
        mu2d *= 1.05;
    }
}